// round 8
// baseline (speedup 1.0000x reference)
#include <cuda_runtime.h>
#include <cuda_fp16.h>
#include <math.h>

#define BB 64
#define MM 2048
#define CC 64
#define HH 128
#define NNZE 32768
#define H3 384
#define PADN 40960   // per-graph padded edge stream capacity (max 32768+3*2048)

// -------- scratch (static device arrays; no runtime malloc) --------
__device__ int           g_cluscnt[BB*CC];
__device__ int           g_clusoff[BB*CC];
__device__ int           g_csplit[BB*CC*4]; // padded-stream start at row quartiles
__device__ unsigned char g_nit[BB*MM];      // per row (cluster order): padded_len/4
__device__ int2          g_csr[BB*PADN];    // cluster-ordered, row-padded edges
__device__ uint2         g_xh[BB*MM*16];    // x in fp16: [row][16 x uint2 = 64 halves]... (32 uint2/row? see k_cvt)
__device__ uint2         g_xh2[BB*MM*16];   // second half of each row (layout split below)
__device__ float         g_xdec[BB*CC*H3];
__device__ float         g_Q[BB*CC*HH];
__device__ float         g_K[BB*CC*HH];
__device__ float         g_V[BB*CC*HH];

// NOTE on layout: a row is 128 halves = 256B = 32 uint2. We keep one linear
// array view by treating g_xh/g_xh2 as a single contiguous region is NOT
// guaranteed, so instead index a single array of 32 uint2 per row built from
// both halves. To keep it simple we only use g_xh (16 uint2 = lanes 0..15)
// and g_xh2 (lanes 16..31).

// ============ K0: convert x fp32 -> fp16 ============
__global__ void __launch_bounds__(256) k_cvt(const float4* __restrict__ x4) {
    int i = blockIdx.x * 256 + threadIdx.x;        // over BB*MM*32 float4s
    float4 v = __ldg(&x4[i]);
    __half2 h0 = __floats2half2_rn(v.x, v.y);
    __half2 h1 = __floats2half2_rn(v.z, v.w);
    uint2 o;
    *reinterpret_cast<__half2*>(&o.x) = h0;
    *reinterpret_cast<__half2*>(&o.y) = h1;
    int row  = i >> 5;          // global row (g*MM + r)
    int lane = i & 31;          // float4 index within row
    if (lane < 16) g_xh [row * 16 + lane]        = o;
    else           g_xh2[row * 16 + (lane - 16)] = o;
}

// ============ K1: build cluster-ordered padded CSR (one CTA / graph) =====
__global__ void __launch_bounds__(1024) k_prep(const int* __restrict__ rows,
                                               const int* __restrict__ cols,
                                               const float* __restrict__ vals,
                                               const int* __restrict__ idx) {
    __shared__ int   hist[MM];
    __shared__ int   cur[MM];
    __shared__ int   ss[1024];
    __shared__ short pos2row[MM];
    __shared__ int   chist[CC], ccur[CC], coffs[CC];
    int g = blockIdx.x, tid = threadIdx.x;
    hist[tid] = 0; hist[tid + 1024] = 0;
    if (tid < CC) chist[tid] = 0;
    __syncthreads();

    const int* r  = rows + g * NNZE;
    const int* ix = idx  + g * MM;
    for (int i = tid; i < NNZE; i += 1024) atomicAdd(&hist[r[i]], 1);
    int i0 = ix[tid], i1 = ix[tid + 1024];
    atomicAdd(&chist[i0], 1);
    atomicAdd(&chist[i1], 1);
    __syncthreads();

    if (tid == 0) {
        int acc = 0;
        for (int c = 0; c < CC; c++) {
            coffs[c] = acc; ccur[c] = acc;
            g_clusoff[g*CC + c] = acc;
            g_cluscnt[g*CC + c] = chist[c];
            acc += chist[c];
        }
    }
    __syncthreads();

    int p0 = atomicAdd(&ccur[i0], 1); pos2row[p0] = (short)tid;
    int p1 = atomicAdd(&ccur[i1], 1); pos2row[p1] = (short)(tid + 1024);
    __syncthreads();

    int r0 = pos2row[2*tid], r1 = pos2row[2*tid + 1];
    int len0 = hist[r0], len1 = hist[r1];
    int l0 = (len0 + 3) & ~3, l1 = (len1 + 3) & ~3;
    int t = l0 + l1;
    ss[tid] = t;
    __syncthreads();
    for (int off = 1; off < 1024; off <<= 1) {
        int v = (tid >= off) ? ss[tid - off] : 0;
        __syncthreads();
        ss[tid] += v;
        __syncthreads();
    }
    int excl = ss[tid] - t;
    int o0 = excl, o1 = excl + l0;
    cur[r0] = o0;  cur[r1] = o1;
    g_nit[g*MM + 2*tid]     = (unsigned char)(l0 >> 2);
    g_nit[g*MM + 2*tid + 1] = (unsigned char)(l1 >> 2);

    int2* cbase = g_csr + (size_t)g * PADN;
    for (int k = len0; k < l0; k++) cbase[o0 + k] = make_int2(0, 0);
    for (int k = len1; k < l1; k++) cbase[o1 + k] = make_int2(0, 0);
    __syncthreads();

    if (tid < CC) {
        int cp = coffs[tid], nr = chist[tid];
        #pragma unroll
        for (int q = 0; q < 4; q++) {
            int qs = (nr * q) >> 2;
            g_csplit[(g*CC + tid)*4 + q] =
                (nr > 0) ? cur[pos2row[cp + qs]] : 0;
        }
    }
    __syncthreads();

    const int*   c = cols + g * NNZE;
    const float* v = vals + g * NNZE;
    for (int i = tid; i < NNZE; i += 1024) {
        int rr = r[i];
        int p = atomicAdd(&cur[rr], 1);
        cbase[p] = make_int2(c[i], __float_as_int(v[i]));
    }
}

// ============ K2: SpMM + pooling, fp16 x gather (halved L2 traffic) ======
// Warp = one row-quartile of one cluster; lane = one float4 (4 halves via
// one uint2 load) of H=128. Edges batched 4/iter (2 int4 + 4 uint2 loads,
// all independent). Accumulation stays fp32.
__global__ void __launch_bounds__(256) k_spmm() {
    __shared__ float comb[2][3][32][8];
    int g = blockIdx.x >> 5;
    int cgrp = blockIdx.x & 31;
    int wid = threadIdx.x >> 5, lane = threadIdx.x & 31;
    int ci = wid >> 2;
    int sub = wid & 3;
    int c = cgrp * 2 + ci;
    int nr  = g_cluscnt[g*CC + c];
    int pos = g_clusoff[g*CC + c];
    int lo = (nr * sub) >> 2, hi = (nr * (sub + 1)) >> 2;
    int eptr = g_csplit[(g*CC + c)*4 + sub];
    const uint2* xq = ((lane < 16) ? g_xh : g_xh2)
                      + (size_t)g * MM * 16 + (lane & 15);
    const int4* cs = (const int4*)(g_csr + (size_t)g * PADN + eptr);
    const unsigned char* nitp = g_nit + g * MM + pos;

    float4 s  = make_float4(0.f, 0.f, 0.f, 0.f);
    float4 mx = make_float4(-INFINITY, -INFINITY, -INFINITY, -INFINITY);

    for (int j0 = lo; j0 < hi; j0 += 32) {
        int lim = min(32, hi - j0);
        int myv = (lane < lim) ? (int)nitp[j0 + lane] : 0;
        for (int j = 0; j < lim; j++) {
            int it = __shfl_sync(0xFFFFFFFFu, myv, j);
            float4 acc = make_float4(0.f, 0.f, 0.f, 0.f);
            #pragma unroll 2
            for (int t = 0; t < it; t++) {
                int4 a = __ldg(cs);
                int4 b = __ldg(cs + 1);
                cs += 2;
                uint2 u0 = __ldg(&xq[(size_t)a.x * 16]);
                uint2 u1 = __ldg(&xq[(size_t)a.z * 16]);
                uint2 u2 = __ldg(&xq[(size_t)b.x * 16]);
                uint2 u3 = __ldg(&xq[(size_t)b.z * 16]);
                float f0 = __int_as_float(a.y), f1 = __int_as_float(a.w);
                float f2 = __int_as_float(b.y), f3 = __int_as_float(b.w);
                float2 p0a = __half22float2(*(__half2*)&u0.x);
                float2 p0b = __half22float2(*(__half2*)&u0.y);
                float2 p1a = __half22float2(*(__half2*)&u1.x);
                float2 p1b = __half22float2(*(__half2*)&u1.y);
                float2 p2a = __half22float2(*(__half2*)&u2.x);
                float2 p2b = __half22float2(*(__half2*)&u2.y);
                float2 p3a = __half22float2(*(__half2*)&u3.x);
                float2 p3b = __half22float2(*(__half2*)&u3.y);
                acc.x += f0*p0a.x + f1*p1a.x + f2*p2a.x + f3*p3a.x;
                acc.y += f0*p0a.y + f1*p1a.y + f2*p2a.y + f3*p3a.y;
                acc.z += f0*p0b.x + f1*p1b.x + f2*p2b.x + f3*p3b.x;
                acc.w += f0*p0b.y + f1*p1b.y + f2*p2b.y + f3*p3b.y;
            }
            s.x += acc.x; s.y += acc.y; s.z += acc.z; s.w += acc.w;
            mx.x = fmaxf(mx.x, acc.x); mx.y = fmaxf(mx.y, acc.y);
            mx.z = fmaxf(mx.z, acc.z); mx.w = fmaxf(mx.w, acc.w);
        }
    }
    if (sub != 0) {
        float* cb = comb[ci][sub - 1][lane];
        cb[0] = s.x;  cb[1] = s.y;  cb[2] = s.z;  cb[3] = s.w;
        cb[4] = mx.x; cb[5] = mx.y; cb[6] = mx.z; cb[7] = mx.w;
    }
    __syncthreads();
    if (sub == 0) {
        #pragma unroll
        for (int w = 0; w < 3; w++) {
            const float* cb = comb[ci][w][lane];
            s.x += cb[0]; s.y += cb[1]; s.z += cb[2]; s.w += cb[3];
            mx.x = fmaxf(mx.x, cb[4]); mx.y = fmaxf(mx.y, cb[5]);
            mx.z = fmaxf(mx.z, cb[6]); mx.w = fmaxf(mx.w, cb[7]);
        }
        float cf = fmaxf((float)nr, 1.f);
        float* xd = g_xdec + (g*CC + c) * H3;
        float4 mean = make_float4(s.x/cf, s.y/cf, s.z/cf, s.w/cf);
        *(float4*)&xd[lane*4]        = mean;
        *(float4*)&xd[HH + lane*4]   = mx;
        *(float4*)&xd[2*HH + lane*4] = s;
    }
}

// ============ packed f32x2 helpers ============
__device__ __forceinline__ void ffma2(unsigned long long& d,
                                      unsigned long long a,
                                      unsigned long long b) {
    asm("fma.rn.f32x2 %0, %1, %2, %0;" : "+l"(d) : "l"(a), "l"(b));
}
__device__ __forceinline__ unsigned long long pack2(float v) {
    unsigned long long r;
    asm("mov.b64 %0, {%1, %1};" : "=l"(r) : "f"(v));
    return r;
}

// ============ K3: Q/K/V = x_dec @ W, grid (64, 3, 2 N-halves) ============
#define XS_LD 68
__global__ void __launch_bounds__(256) k_gemm(const float* __restrict__ Wq,
                                              const float* __restrict__ Wk,
                                              const float* __restrict__ Wv) {
    extern __shared__ float sm[];
    float* xsA = sm;
    float* ws  = sm + 64 * XS_LD;
    int g = blockIdx.x, which = blockIdx.y, zh = blockIdx.z;
    const float* W = ((which == 0) ? Wq : (which == 1) ? Wk : Wv) + zh * 64;
    float* out = ((which == 0) ? g_Q : (which == 1) ? g_K : g_V)
                 + g * CC * HH + zh * 64;
    const float* xd = g_xdec + g * CC * H3;
    int tid = threadIdx.x;
    int ty = tid >> 4, tx = tid & 15;

    unsigned long long acc[4][2];
    #pragma unroll
    for (int i = 0; i < 4; i++) { acc[i][0] = 0ull; acc[i][1] = 0ull; }

    for (int kt = 0; kt < H3; kt += 64) {
        __syncthreads();
        for (int i = tid; i < 64 * 64; i += 256) {
            int rr = i >> 6, kk = i & 63;
            xsA[kk * XS_LD + rr] = xd[rr * H3 + kt + kk];
        }
        for (int i = tid; i < 64 * 16; i += 256) {
            int row = i >> 4, cidx = i & 15;
            *(float4*)&ws[row * 64 + cidx * 4] =
                *(const float4*)&W[(kt + row) * HH + cidx * 4];
        }
        __syncthreads();
        #pragma unroll 8
        for (int kk = 0; kk < 64; kk++) {
            float4 av = *(const float4*)&xsA[kk * XS_LD + ty * 4];
            ulonglong2 b = *(const ulonglong2*)&ws[kk * 64 + tx * 4];
            unsigned long long pa0 = pack2(av.x), pa1 = pack2(av.y);
            unsigned long long pa2 = pack2(av.z), pa3 = pack2(av.w);
            ffma2(acc[0][0], pa0, b.x);  ffma2(acc[0][1], pa0, b.y);
            ffma2(acc[1][0], pa1, b.x);  ffma2(acc[1][1], pa1, b.y);
            ffma2(acc[2][0], pa2, b.x);  ffma2(acc[2][1], pa2, b.y);
            ffma2(acc[3][0], pa3, b.x);  ffma2(acc[3][1], pa3, b.y);
        }
    }
    #pragma unroll
    for (int i = 0; i < 4; i++) {
        ulonglong2 o; o.x = acc[i][0]; o.y = acc[i][1];
        *(ulonglong2*)&out[(ty*4 + i) * HH + tx * 4] = o;
    }
}

// ============ K4: attention, float4 staging + warp-parallel softmax ======
__global__ void __launch_bounds__(256) k_attn(float* __restrict__ out) {
    extern __shared__ float sm[];
    float* Qs = sm;                   // 16 * 132
    float* Ks = Qs + 16 * 132;        // 64 * 132
    float* Vs = Ks + 64 * 132;        // 64 * 132
    float* Ss = Vs + 64 * 132;        // 16 * 68
    int g = blockIdx.x, rh = blockIdx.y * 16, tid = threadIdx.x;
    const float4* Qg = (const float4*)(g_Q + g * CC * HH + rh * HH);
    const float4* Kg = (const float4*)(g_K + g * CC * HH);
    const float4* Vg = (const float4*)(g_V + g * CC * HH);

    for (int i = tid; i < 16 * 32; i += 256) {
        int r = i >> 5, cc = i & 31;
        ((float4*)Qs)[r * 33 + cc] = __ldg(&Qg[r * 32 + cc]);
    }
    for (int i = tid; i < 64 * 32; i += 256) {
        int r = i >> 5, cc = i & 31;
        ((float4*)Ks)[r * 33 + cc] = __ldg(&Kg[r * 32 + cc]);
        ((float4*)Vs)[r * 33 + cc] = __ldg(&Vg[r * 32 + cc]);
    }
    __syncthreads();

    int r = tid & 15, grp = tid >> 4;      // 16 rows x 16 col-groups
    {
        float sacc[4] = {0.f, 0.f, 0.f, 0.f};
        const float4* q4 = (const float4*)Qs + r * 33;
        const float4* k4 = (const float4*)Ks;
        #pragma unroll 4
        for (int h4 = 0; h4 < 32; h4++) {
            float4 q = q4[h4];
            #pragma unroll
            for (int cc = 0; cc < 4; cc++) {
                float4 k = k4[(grp*4 + cc) * 33 + h4];
                sacc[cc] += q.x*k.x + q.y*k.y + q.z*k.z + q.w*k.w;
            }
        }
        const float scale = 0.08838834764831845f;   // 1/sqrt(128)
        #pragma unroll
        for (int cc = 0; cc < 4; cc++) Ss[r*68 + grp*4 + cc] = sacc[cc] * scale;
    }
    __syncthreads();
    // warp-parallel softmax: 8 warps x 2 rows; 16 lanes per row, 4 cols/lane
    {
        int wid = tid >> 5, lane = tid & 31;
        int rr = wid * 2 + (lane >> 4);
        int l16 = lane & 15;
        float v0 = Ss[rr*68 + l16];
        float v1 = Ss[rr*68 + l16 + 16];
        float v2 = Ss[rr*68 + l16 + 32];
        float v3 = Ss[rr*68 + l16 + 48];
        float m = fmaxf(fmaxf(v0, v1), fmaxf(v2, v3));
        #pragma unroll
        for (int o = 1; o < 16; o <<= 1)
            m = fmaxf(m, __shfl_xor_sync(0xFFFFFFFFu, m, o));
        float e0 = __expf(v0 - m), e1 = __expf(v1 - m);
        float e2 = __expf(v2 - m), e3 = __expf(v3 - m);
        float sum = e0 + e1 + e2 + e3;
        #pragma unroll
        for (int o = 1; o < 16; o <<= 1)
            sum += __shfl_xor_sync(0xFFFFFFFFu, sum, o);
        float inv = 1.f / sum;
        Ss[rr*68 + l16]      = e0 * inv;
        Ss[rr*68 + l16 + 16] = e1 * inv;
        Ss[rr*68 + l16 + 32] = e2 * inv;
        Ss[rr*68 + l16 + 48] = e3 * inv;
    }
    __syncthreads();
    {
        float4 a0 = make_float4(0.f,0.f,0.f,0.f), a1 = a0;
        const float4* v4 = (const float4*)Vs;
        #pragma unroll 4
        for (int c = 0; c < CC; c++) {
            float p = Ss[r*68 + c];
            float4 v0 = v4[c * 33 + grp * 2];
            float4 v1 = v4[c * 33 + grp * 2 + 1];
            a0.x += p*v0.x; a0.y += p*v0.y; a0.z += p*v0.z; a0.w += p*v0.w;
            a1.x += p*v1.x; a1.y += p*v1.y; a1.z += p*v1.z; a1.w += p*v1.w;
        }
        float4* o4 = (float4*)out + g * 2048 + (rh + r) * 32 + grp * 2;
        o4[0] = a0; o4[1] = a1;
    }
}

extern "C" void kernel_launch(void* const* d_in, const int* in_sizes, int n_in,
                              void* d_out, int out_size) {
    const float* x    = (const float*)d_in[0];
    const int*   rows = (const int*)d_in[3];
    const int*   cols = (const int*)d_in[4];
    const float* vals = (const float*)d_in[5];
    const int*   idx  = (const int*)d_in[6];
    const float* Wq   = (const float*)d_in[7];
    const float* Wk   = (const float*)d_in[8];
    const float* Wv   = (const float*)d_in[9];
    float* out = (float*)d_out;

    static const int GEMM_SMEM = (64*XS_LD + 64*64) * 4;            // 33792 B
    static const int ATTN_SMEM = ((16 + 2*64) * 132 + 16*68) * 4;   // 80384 B
    cudaFuncSetAttribute(k_gemm, cudaFuncAttributeMaxDynamicSharedMemorySize, GEMM_SMEM);
    cudaFuncSetAttribute(k_attn, cudaFuncAttributeMaxDynamicSharedMemorySize, ATTN_SMEM);

    k_cvt<<<BB*MM*32/256, 256>>>((const float4*)x);
    k_prep<<<BB, 1024>>>(rows, cols, vals, idx);
    k_spmm<<<BB * 32, 256>>>();
    k_gemm<<<dim3(BB, 3, 2), 256, GEMM_SMEM>>>(Wq, Wk, Wv);
    k_attn<<<dim3(BB, 4), 256, ATTN_SMEM>>>(out);
}